// round 14
// baseline (speedup 1.0000x reference)
#include <cuda_runtime.h>
#include <cuda_fp16.h>
#include <cstdint>

#define N_NODES 50000
#define N_EDGES 1600000
#define F_INDIM 1280
#define HDIM    128
#define NGRAPH  64
#define OUT_DIM 2
#define TP_NORM 0.024933891662820262f  /* (0.5/sqrt(pi))/sqrt(128) */

#define TILE_SPLIT 196                     /* m-tiles in half1 */
#define NODE_SPLIT (TILE_SPLIT * 128)      /* 25088 */
#define GEMM_TILES ((N_NODES + 127) / 128) /* 391 */
#define PERSIST_GRID 304                   /* ~2 CTAs per SM */

// ---------------- device scratch (no allocations allowed) ----------------
__device__ __half g_h16a[N_NODES * HDIM];   // ping-pong feature buffers
__device__ __half g_h16b[N_NODES * HDIM];
__device__ __half g_agg[N_NODES * HDIM];
__device__ int    g_cnt[N_NODES];
__device__ int    g_cursor[N_NODES];
__device__ int    g_rowptr[N_NODES + 1];
__device__ int    g_col[N_EDGES];
__device__ float  g_inv[N_NODES];
__device__ float  g_zsum[NGRAPH * HDIM];
__device__ int    g_zcnt[NGRAPH];
__device__ int    g_tilectr;
__device__ __half g_Bh[F_INDIM * HDIM];
__device__ __half g_Bl[F_INDIM * HDIM];
__device__ __half g_W1h[HDIM * HDIM], g_W1l[HDIM * HDIM];
__device__ __half g_W2h[HDIM * HDIM], g_W2l[HDIM * HDIM];
__device__ __half g_W3h[HDIM * HDIM], g_W3l[HDIM * HDIM];

// ---------------- small setup kernels ----------------
__global__ void k_zero() {
    int i = blockIdx.x * blockDim.x + threadIdx.x;
    if (i < N_NODES) { g_cnt[i] = 0; g_cursor[i] = 0; }
    if (i < NGRAPH * HDIM) g_zsum[i] = 0.0f;
    if (i < NGRAPH) g_zcnt[i] = 0;
}

__global__ void k_ctr0() { g_tilectr = 0; }

__global__ void k_count(const int* __restrict__ ei, const int* __restrict__ batch) {
    int e = blockIdx.x * blockDim.x + threadIdx.x;
    if (e < N_EDGES) atomicAdd(&g_cnt[ei[N_EDGES + e]], 1);
    if (e < N_NODES) atomicAdd(&g_zcnt[batch[e]], 1);
}

__global__ void k_scan() {
    __shared__ int warp_sums[32];
    __shared__ int s_carry;
    int tid = threadIdx.x, lane = tid & 31, wid = tid >> 5;
    if (tid == 0) s_carry = 0;
    __syncthreads();
    for (int base = 0; base < N_NODES; base += 1024) {
        int i = base + tid;
        int v = (i < N_NODES) ? g_cnt[i] : 0;
        if (i < N_NODES) g_inv[i] = 1.0f / (float)max(v, 1);
        int x = v;
        #pragma unroll
        for (int off = 1; off < 32; off <<= 1) {
            int y = __shfl_up_sync(0xffffffffu, x, off);
            if (lane >= off) x += y;
        }
        if (lane == 31) warp_sums[wid] = x;
        __syncthreads();
        if (wid == 0) {
            int w = warp_sums[lane];
            #pragma unroll
            for (int off = 1; off < 32; off <<= 1) {
                int y = __shfl_up_sync(0xffffffffu, w, off);
                if (lane >= off) w += y;
            }
            warp_sums[lane] = w;
        }
        __syncthreads();
        int incl = x + (wid > 0 ? warp_sums[wid - 1] : 0);
        int excl = incl - v;
        if (i < N_NODES) g_rowptr[i] = s_carry + excl;
        __syncthreads();
        if (tid == 0) s_carry += warp_sums[31];
        __syncthreads();
    }
    if (threadIdx.x == 0) g_rowptr[N_NODES] = s_carry;
}

__global__ void k_build(const int* __restrict__ ei) {
    int e = blockIdx.x * blockDim.x + threadIdx.x;
    if (e >= N_EDGES) return;
    int d = ei[N_EDGES + e];
    int s = ei[e];
    int pos = g_rowptr[d] + atomicAdd(&g_cursor[d], 1);
    g_col[pos] = s;
}

// ---------------- split fp32 weight -> (hi, lo) fp16 ----------------
__global__ void k_split(const float* __restrict__ w, int n,
                        __half* __restrict__ hi, __half* __restrict__ lo) {
    int i = blockIdx.x * blockDim.x + threadIdx.x;
    if (i >= n) return;
    float x = w[i];
    __half h = __float2half_rn(x);
    hi[i] = h;
    lo[i] = __float2half_rn(x - __half2float(h));
}

// ---------------- mma helpers ----------------
__device__ __forceinline__ void ldsm4(uint32_t (&r)[4], uint32_t addr) {
    asm volatile("ldmatrix.sync.aligned.m8n8.x4.shared.b16 {%0,%1,%2,%3}, [%4];"
                 : "=r"(r[0]), "=r"(r[1]), "=r"(r[2]), "=r"(r[3]) : "r"(addr));
}
__device__ __forceinline__ void ldsm4t(uint32_t (&r)[4], uint32_t addr) {
    asm volatile("ldmatrix.sync.aligned.m8n8.x4.trans.shared.b16 {%0,%1,%2,%3}, [%4];"
                 : "=r"(r[0]), "=r"(r[1]), "=r"(r[2]), "=r"(r[3]) : "r"(addr));
}
__device__ __forceinline__ void mma16816h(float (&c)[4], const uint32_t (&a)[4],
                                          uint32_t b0, uint32_t b1) {
    asm volatile(
        "mma.sync.aligned.m16n8k16.row.col.f32.f16.f16.f32 "
        "{%0,%1,%2,%3}, {%4,%5,%6,%7}, {%8,%9}, {%0,%1,%2,%3};"
        : "+f"(c[0]), "+f"(c[1]), "+f"(c[2]), "+f"(c[3])
        : "r"(a[0]), "r"(a[1]), "r"(a[2]), "r"(a[3]), "r"(b0), "r"(b1));
}

#define SA_STR 40
#define SB_STR 136

// ---------------- tensor-core GEMM (fp16, 2-term weight split, single-buffer) --------------
// persist!=0: CTAs loop over tiles via g_tilectr (counter pre-zeroed on same stream).
// persist==0: one tile per CTA (blockIdx.x + tile_off), exactly R9 behavior.
__global__ void __launch_bounds__(256, 2) k_gemm_tc(
    const void* __restrict__ Av,
    const __half* __restrict__ Bh, const __half* __restrict__ Bl,
    const float* __restrict__ bias, void* __restrict__ Cv,
    int M, int K, float alpha, int do_relu, int in_half, int out_half,
    int tile_off, int num_tiles, int persist, const int* __restrict__ pool_batch)
{
    __shared__ __half sA[128 * SA_STR];
    __shared__ __half sBh[32 * SB_STR];
    __shared__ __half sBl[32 * SB_STR];
    __shared__ int s_tile;

    const int tid  = threadIdx.x;
    const int lane = tid & 31;
    const int warp = tid >> 5;
    const int wm   = warp & 3;
    const int wn   = warp >> 2;

    const int ar = tid >> 1;
    const int ac = (tid & 1) * 16;
    const int br = tid >> 3;
    const int bc = (tid & 7) * 16;

    const uint32_t baseA  = (uint32_t)__cvta_generic_to_shared(sA);
    const uint32_t baseBh = (uint32_t)__cvta_generic_to_shared(sBh);
    const uint32_t baseBl = (uint32_t)__cvta_generic_to_shared(sBl);

    const int T = K >> 5;
    const float*  Af = (const float*)Av;
    const __half* Ah = (const __half*)Av;

    int tile = blockIdx.x + tile_off;

    for (;;) {
        if (persist) {
            __syncthreads();                 // prior tile fully done with smem
            if (tid == 0) s_tile = atomicAdd(&g_tilectr, 1);
            __syncthreads();
            tile = s_tile;
            if (tile >= num_tiles) return;   // uniform exit
        }

        const int m0   = tile * 128;
        const int arow = m0 + ar;
        const bool aok = (arow < M);

        float acc[2][8][4];
        #pragma unroll
        for (int t = 0; t < 2; t++)
            #pragma unroll
            for (int n = 0; n < 8; n++)
                #pragma unroll
                for (int j = 0; j < 4; j++) acc[t][n][j] = 0.0f;

        uint4 ha0, ha1;
        uint4 pbh0, pbh1, pbl0, pbl1;

        // ---- prologue: load tile 0 ----
        {
            ha0 = make_uint4(0u, 0u, 0u, 0u); ha1 = ha0;
            if (aok) {
                if (in_half) {
                    const uint4* ap = (const uint4*)(Ah + (size_t)arow * K + ac);
                    ha0 = ap[0]; ha1 = ap[1];
                } else {
                    const float4* ap = (const float4*)(Af + (size_t)arow * K + ac);
                    float4 f0 = ap[0], f1 = ap[1], f2 = ap[2], f3 = ap[3];
                    __half2 h0 = __floats2half2_rn(f0.x, f0.y);
                    __half2 h1 = __floats2half2_rn(f0.z, f0.w);
                    __half2 h2 = __floats2half2_rn(f1.x, f1.y);
                    __half2 h3 = __floats2half2_rn(f1.z, f1.w);
                    __half2 h4 = __floats2half2_rn(f2.x, f2.y);
                    __half2 h5 = __floats2half2_rn(f2.z, f2.w);
                    __half2 h6 = __floats2half2_rn(f3.x, f3.y);
                    __half2 h7 = __floats2half2_rn(f3.z, f3.w);
                    ha0 = make_uint4(*(uint32_t*)&h0, *(uint32_t*)&h1, *(uint32_t*)&h2, *(uint32_t*)&h3);
                    ha1 = make_uint4(*(uint32_t*)&h4, *(uint32_t*)&h5, *(uint32_t*)&h6, *(uint32_t*)&h7);
                }
            }
            const uint4* bph = (const uint4*)(Bh + (size_t)br * HDIM + bc);
            const uint4* bpl = (const uint4*)(Bl + (size_t)br * HDIM + bc);
            pbh0 = bph[0]; pbh1 = bph[1];
            pbl0 = bpl[0]; pbl1 = bpl[1];
        }

        for (int t = 0; t < T; t++) {
            {
                uint4* da = (uint4*)&sA[ar * SA_STR + ac];
                da[0] = ha0; da[1] = ha1;
                *(uint4*)&sBh[br * SB_STR + bc]     = pbh0;
                *(uint4*)&sBh[br * SB_STR + bc + 8] = pbh1;
                *(uint4*)&sBl[br * SB_STR + bc]     = pbl0;
                *(uint4*)&sBl[br * SB_STR + bc + 8] = pbl1;
            }
            __syncthreads();

            if (t + 1 < T) {
                const int k0 = (t + 1) << 5;
                ha0 = make_uint4(0u, 0u, 0u, 0u); ha1 = ha0;
                if (aok) {
                    if (in_half) {
                        const uint4* ap = (const uint4*)(Ah + (size_t)arow * K + k0 + ac);
                        ha0 = ap[0]; ha1 = ap[1];
                    } else {
                        const float4* ap = (const float4*)(Af + (size_t)arow * K + k0 + ac);
                        float4 f0 = ap[0], f1 = ap[1], f2 = ap[2], f3 = ap[3];
                        __half2 h0 = __floats2half2_rn(f0.x, f0.y);
                        __half2 h1 = __floats2half2_rn(f0.z, f0.w);
                        __half2 h2 = __floats2half2_rn(f1.x, f1.y);
                        __half2 h3 = __floats2half2_rn(f1.z, f1.w);
                        __half2 h4 = __floats2half2_rn(f2.x, f2.y);
                        __half2 h5 = __floats2half2_rn(f2.z, f2.w);
                        __half2 h6 = __floats2half2_rn(f3.x, f3.y);
                        __half2 h7 = __floats2half2_rn(f3.z, f3.w);
                        ha0 = make_uint4(*(uint32_t*)&h0, *(uint32_t*)&h1, *(uint32_t*)&h2, *(uint32_t*)&h3);
                        ha1 = make_uint4(*(uint32_t*)&h4, *(uint32_t*)&h5, *(uint32_t*)&h6, *(uint32_t*)&h7);
                    }
                }
                const uint4* bph = (const uint4*)(Bh + (size_t)(k0 + br) * HDIM + bc);
                const uint4* bpl = (const uint4*)(Bl + (size_t)(k0 + br) * HDIM + bc);
                pbh0 = bph[0]; pbh1 = bph[1];
                pbl0 = bpl[0]; pbl1 = bpl[1];
            }

            #pragma unroll
            for (int ks = 0; ks < 2; ks++) {
                uint32_t a[2][4];
                #pragma unroll
                for (int tt = 0; tt < 2; tt++) {
                    int r = wm * 32 + tt * 16 + (lane & 15);
                    int c = ks * 16 + (lane >> 4) * 8;
                    ldsm4(a[tt], baseA + (r * SA_STR + c) * 2);
                }
                #pragma unroll
                for (int p = 0; p < 4; p++) {
                    int r = ks * 16 + (lane & 7) + ((lane >> 3) & 1) * 8;
                    int c = wn * 64 + p * 16 + (lane >> 4) * 8;
                    uint32_t bh[4], bl[4];
                    ldsm4t(bh, baseBh + (r * SB_STR + c) * 2);
                    ldsm4t(bl, baseBl + (r * SB_STR + c) * 2);
                    #pragma unroll
                    for (int tt = 0; tt < 2; tt++) {
                        mma16816h(acc[tt][2 * p],     a[tt], bh[0], bh[1]);
                        mma16816h(acc[tt][2 * p],     a[tt], bl[0], bl[1]);
                        mma16816h(acc[tt][2 * p + 1], a[tt], bh[2], bh[3]);
                        mma16816h(acc[tt][2 * p + 1], a[tt], bl[2], bl[3]);
                    }
                }
            }
            __syncthreads();
        }

        // ---- epilogue ----
        #pragma unroll
        for (int t = 0; t < 2; t++) {
            #pragma unroll
            for (int nt = 0; nt < 8; nt++) {
                int col = wn * 64 + nt * 8 + (lane & 3) * 2;
                float b0 = 0.f, b1 = 0.f;
                if (bias) { b0 = bias[col]; b1 = bias[col + 1]; }
                int r0 = m0 + wm * 32 + t * 16 + (lane >> 2);
                int r1 = r0 + 8;
                float v00 = acc[t][nt][0] * alpha + b0;
                float v01 = acc[t][nt][1] * alpha + b1;
                float v10 = acc[t][nt][2] * alpha + b0;
                float v11 = acc[t][nt][3] * alpha + b1;
                if (do_relu) {
                    v00 = fmaxf(v00, 0.f); v01 = fmaxf(v01, 0.f);
                    v10 = fmaxf(v10, 0.f); v11 = fmaxf(v11, 0.f);
                }
                if (pool_batch) {
                    if (r0 < M) {
                        int g = pool_batch[r0];
                        atomicAdd(&g_zsum[g * HDIM + col], v00);
                        atomicAdd(&g_zsum[g * HDIM + col + 1], v01);
                    }
                    if (r1 < M) {
                        int g = pool_batch[r1];
                        atomicAdd(&g_zsum[g * HDIM + col], v10);
                        atomicAdd(&g_zsum[g * HDIM + col + 1], v11);
                    }
                } else if (out_half) {
                    __half* C = (__half*)Cv;
                    if (r0 < M) {
                        __half2 o = __floats2half2_rn(v00, v01);
                        *(__half2*)&C[(size_t)r0 * HDIM + col] = o;
                    }
                    if (r1 < M) {
                        __half2 o = __floats2half2_rn(v10, v11);
                        *(__half2*)&C[(size_t)r1 * HDIM + col] = o;
                    }
                } else {
                    float* C = (float*)Cv;
                    if (r0 < M) { float2 o = {v00, v01}; *(float2*)&C[(size_t)r0 * HDIM + col] = o; }
                    if (r1 < M) { float2 o = {v10, v11}; *(float2*)&C[(size_t)r1 * HDIM + col] = o; }
                }
            }
        }

        if (!persist) return;
    }
}

// ---------------- CSR mean-aggregation over node range [node0, node1) --------------------
__global__ void __launch_bounds__(256) k_agg(const __half* __restrict__ hin,
                                             __half* __restrict__ aout,
                                             int node0, int node1)
{
    int gt = blockIdx.x * 256 + threadIdx.x;
    int node = node0 + (gt >> 5);
    int lane = gt & 31;
    if (node >= node1) return;
    int beg = g_rowptr[node];
    int end = g_rowptr[node + 1];
    float ax = 0.f, ay = 0.f, az = 0.f, aw = 0.f;
    int e = beg;
    for (; e + 4 <= end; e += 4) {
        int s0 = __ldg(&g_col[e]);
        int s1 = __ldg(&g_col[e + 1]);
        int s2 = __ldg(&g_col[e + 2]);
        int s3 = __ldg(&g_col[e + 3]);
        uint2 u0 = *(const uint2*)&hin[(size_t)s0 * HDIM + lane * 4];
        uint2 u1 = *(const uint2*)&hin[(size_t)s1 * HDIM + lane * 4];
        uint2 u2 = *(const uint2*)&hin[(size_t)s2 * HDIM + lane * 4];
        uint2 u3 = *(const uint2*)&hin[(size_t)s3 * HDIM + lane * 4];
        float2 a0 = __half22float2(*(__half2*)&u0.x), b0 = __half22float2(*(__half2*)&u0.y);
        float2 a1 = __half22float2(*(__half2*)&u1.x), b1 = __half22float2(*(__half2*)&u1.y);
        float2 a2 = __half22float2(*(__half2*)&u2.x), b2 = __half22float2(*(__half2*)&u2.y);
        float2 a3 = __half22float2(*(__half2*)&u3.x), b3 = __half22float2(*(__half2*)&u3.y);
        ax += a0.x + a1.x + a2.x + a3.x;
        ay += a0.y + a1.y + a2.y + a3.y;
        az += b0.x + b1.x + b2.x + b3.x;
        aw += b0.y + b1.y + b2.y + b3.y;
    }
    for (; e < end; e++) {
        int s = __ldg(&g_col[e]);
        uint2 u = *(const uint2*)&hin[(size_t)s * HDIM + lane * 4];
        float2 a = __half22float2(*(__half2*)&u.x), b = __half22float2(*(__half2*)&u.y);
        ax += a.x; ay += a.y; az += b.x; aw += b.y;
    }
    float sc = g_inv[node];
    __half2 o0 = __floats2half2_rn(ax * sc, ay * sc);
    __half2 o1 = __floats2half2_rn(az * sc, aw * sc);
    uint2 o;
    o.x = *(uint32_t*)&o0;
    o.y = *(uint32_t*)&o1;
    *(uint2*)&aout[(size_t)node * HDIM + lane * 4] = o;
}

// ---------------- classifier head: one block per graph ----------------
__global__ void __launch_bounds__(128) k_head(
    const float* __restrict__ c1w, const float* __restrict__ c1b,
    const float* __restrict__ c2w, const float* __restrict__ c2b,
    const float* __restrict__ c3w, const float* __restrict__ c3b,
    float* __restrict__ dout)
{
    __shared__ float z[HDIM], o1[HDIM], o2[HDIM];
    int g = blockIdx.x;
    int c = threadIdx.x;
    float cnt = (float)max(g_zcnt[g], 1);
    float zv = g_zsum[g * HDIM + c] / cnt;
    z[c] = zv;
    dout[NGRAPH * OUT_DIM + g * HDIM + c] = zv;
    __syncthreads();
    float s = c1b[c];
    #pragma unroll 8
    for (int k = 0; k < HDIM; k++) s += z[k] * c1w[k * HDIM + c];
    o1[c] = fmaxf(s, 0.f);
    __syncthreads();
    s = c2b[c];
    #pragma unroll 8
    for (int k = 0; k < HDIM; k++) s += o1[k] * c2w[k * HDIM + c];
    o2[c] = fmaxf(s, 0.f);
    __syncthreads();
    if (c < OUT_DIM) {
        s = c3b[c];
        #pragma unroll 8
        for (int k = 0; k < HDIM; k++) s += o2[k] * c3w[k * OUT_DIM + c];
        dout[g * OUT_DIM + c] = s;
    }
}

// ---------------- side stream/events (created at static init) ----------------
static cudaStream_t s_side = nullptr;
static cudaEvent_t  s_evFork = nullptr, s_evJoin = nullptr;
static cudaEvent_t  s_evA[4], s_evB[4];
namespace {
struct SideInit {
    SideInit() {
        cudaStreamCreateWithFlags(&s_side, cudaStreamNonBlocking);
        cudaEventCreateWithFlags(&s_evFork, cudaEventDisableTiming);
        cudaEventCreateWithFlags(&s_evJoin, cudaEventDisableTiming);
        for (int i = 0; i < 4; i++) {
            cudaEventCreateWithFlags(&s_evA[i], cudaEventDisableTiming);
            cudaEventCreateWithFlags(&s_evB[i], cudaEventDisableTiming);
        }
    }
};
static SideInit s_sideInit;
}

// ---------------- launch ----------------
extern "C" void kernel_launch(void* const* d_in, const int* in_sizes, int n_in,
                              void* d_out, int out_size)
{
    const float* x     = (const float*)d_in[0];
    const int*   ei    = (const int*)  d_in[2];
    const int*   batch = (const int*)  d_in[3];
    const float* lin_w = (const float*)d_in[4];
    const float* lin_b = (const float*)d_in[5];
    const float* tp_w1 = (const float*)d_in[6];
    const float* tp_w2 = (const float*)d_in[7];
    const float* tp_w3 = (const float*)d_in[8];
    const float* c1w   = (const float*)d_in[9];
    const float* c1b   = (const float*)d_in[10];
    const float* c2w   = (const float*)d_in[11];
    const float* c2b   = (const float*)d_in[12];
    const float* c3w   = (const float*)d_in[13];
    const float* c3b   = (const float*)d_in[14];
    float* out = (float*)d_out;

    __half *hA, *hB, *agg, *pBh, *pBl, *pW1h, *pW1l, *pW2h, *pW2l, *pW3h, *pW3l;
    cudaGetSymbolAddress((void**)&hA, g_h16a);
    cudaGetSymbolAddress((void**)&hB, g_h16b);
    cudaGetSymbolAddress((void**)&agg, g_agg);
    cudaGetSymbolAddress((void**)&pBh, g_Bh);
    cudaGetSymbolAddress((void**)&pBl, g_Bl);
    cudaGetSymbolAddress((void**)&pW1h, g_W1h);
    cudaGetSymbolAddress((void**)&pW1l, g_W1l);
    cudaGetSymbolAddress((void**)&pW2h, g_W2h);
    cudaGetSymbolAddress((void**)&pW2l, g_W2l);
    cudaGetSymbolAddress((void**)&pW3h, g_W3h);
    cudaGetSymbolAddress((void**)&pW3l, g_W3l);

    const int TB = 256;
    const int T1 = TILE_SPLIT;              // 196 tiles -> rows [0, 25088)
    const int T2 = GEMM_TILES - TILE_SPLIT; // 195 tiles -> rows [25088, 50000)
    const int aggGrid1 = (NODE_SPLIT * 32 + TB - 1) / TB;
    const int aggGrid2 = ((N_NODES - NODE_SPLIT) * 32 + TB - 1) / TB;

    // ---- fork side stream: CSR build + tp-weight splits ----
    cudaEventRecord(s_evFork, 0);
    cudaStreamWaitEvent(s_side, s_evFork, 0);

    k_zero<<<(N_NODES + TB - 1) / TB, TB, 0, s_side>>>();
    k_count<<<(N_EDGES + TB - 1) / TB, TB, 0, s_side>>>(ei, batch);
    k_scan<<<1, 1024, 0, s_side>>>();
    k_build<<<(N_EDGES + TB - 1) / TB, TB, 0, s_side>>>(ei);
    k_split<<<(HDIM * HDIM + TB - 1) / TB, TB, 0, s_side>>>(tp_w1, HDIM * HDIM, pW1h, pW1l);
    k_split<<<(HDIM * HDIM + TB - 1) / TB, TB, 0, s_side>>>(tp_w2, HDIM * HDIM, pW2h, pW2l);
    k_split<<<(HDIM * HDIM + TB - 1) / TB, TB, 0, s_side>>>(tp_w3, HDIM * HDIM, pW3h, pW3l);
    cudaEventRecord(s_evJoin, s_side);

    // ---- main stream: lin split + persistent lin GEMM -> buffer A ----
    k_split<<<(F_INDIM * HDIM + TB - 1) / TB, TB>>>(lin_w, F_INDIM * HDIM, pBh, pBl);
    k_ctr0<<<1, 1>>>();
    k_gemm_tc<<<PERSIST_GRID, TB>>>(x, pBh, pBl, lin_b, hA, N_NODES, F_INDIM,
                                    1.0f, 1, 0, 1, 0, GEMM_TILES, 1, nullptr);

    cudaStreamWaitEvent(0, s_evJoin, 0);

    // ---- convs with split-node agg/GEMM overlap; features ping-pong hA <-> hB ----
    const __half* Wh[3] = {pW1h, pW2h, pW3h};
    const __half* Wl[3] = {pW1l, pW2l, pW3l};
    __half* cur = hA;
    __half* nxt = hB;
    for (int k = 0; k < 3; k++) {
        int relu = (k < 2) ? 1 : 0;
        const int* pool = (k == 2) ? batch : nullptr;
        int oh = (k == 2) ? 0 : 1;
        void* cout = (k == 2) ? nullptr : (void*)nxt;

        cudaEventRecord(s_evA[k], 0);
        cudaStreamWaitEvent(s_side, s_evA[k], 0);

        // aggs read cur -> write agg; GEMMs read agg -> write nxt (no WAR)
        k_agg<<<aggGrid2, TB, 0, s_side>>>(cur, agg, NODE_SPLIT, N_NODES);
        k_agg<<<aggGrid1, TB, 0, 0>>>(cur, agg, 0, NODE_SPLIT);

        k_gemm_tc<<<T1, TB, 0, 0>>>(agg, Wh[k], Wl[k], nullptr, cout,
                                    N_NODES, HDIM, TP_NORM, relu, 1, oh,
                                    0, T1, 0, pool);
        k_gemm_tc<<<T2, TB, 0, s_side>>>(agg, Wh[k], Wl[k], nullptr, cout,
                                         N_NODES, HDIM, TP_NORM, relu, 1, oh,
                                         TILE_SPLIT, GEMM_TILES, 0, pool);

        cudaEventRecord(s_evB[k], s_side);
        cudaStreamWaitEvent(0, s_evB[k], 0);

        __half* tmp = cur; cur = nxt; nxt = tmp;
    }

    // head
    k_head<<<NGRAPH, HDIM>>>(c1w, c1b, c2w, c2b, c3w, c3b, out);
}

// round 15
// speedup vs baseline: 1.4842x; 1.4842x over previous
#include <cuda_runtime.h>
#include <cuda_fp16.h>
#include <cstdint>

#define N_NODES 50000
#define N_EDGES 1600000
#define F_INDIM 1280
#define HDIM    128
#define NGRAPH  64
#define OUT_DIM 2
#define TP_NORM 0.024933891662820262f  /* (0.5/sqrt(pi))/sqrt(128) */

#define TILE_SPLIT 196                     /* m-tiles in half1 */
#define NODE_SPLIT (TILE_SPLIT * 128)      /* 25088 */
#define GEMM_TILES ((N_NODES + 127) / 128) /* 391 */

// ---------------- device scratch (no allocations allowed) ----------------
__device__ __half g_h16a[N_NODES * HDIM];   // ping-pong feature buffers
__device__ __half g_h16b[N_NODES * HDIM];
__device__ __half g_agg[N_NODES * HDIM];
__device__ int    g_cnt[N_NODES];
__device__ int    g_cursor[N_NODES];
__device__ int    g_rowptr[N_NODES + 1];
__device__ int    g_col[N_EDGES];
__device__ float  g_inv[N_NODES];
__device__ float  g_zsum[NGRAPH * HDIM];
__device__ int    g_zcnt[NGRAPH];
__device__ __half g_Bh[F_INDIM * HDIM];
__device__ __half g_Bl[F_INDIM * HDIM];
__device__ __half g_W1h[HDIM * HDIM], g_W1l[HDIM * HDIM];
__device__ __half g_W2h[HDIM * HDIM], g_W2l[HDIM * HDIM];
__device__ __half g_W3h[HDIM * HDIM], g_W3l[HDIM * HDIM];

// ---------------- small setup kernels ----------------
__global__ void k_zero() {
    int i = blockIdx.x * blockDim.x + threadIdx.x;
    if (i < N_NODES) { g_cnt[i] = 0; g_cursor[i] = 0; }
    if (i < NGRAPH * HDIM) g_zsum[i] = 0.0f;
    if (i < NGRAPH) g_zcnt[i] = 0;
}

__global__ void k_count(const int* __restrict__ ei, const int* __restrict__ batch) {
    int e = blockIdx.x * blockDim.x + threadIdx.x;
    if (e < N_EDGES) atomicAdd(&g_cnt[ei[N_EDGES + e]], 1);
    if (e < N_NODES) atomicAdd(&g_zcnt[batch[e]], 1);
}

__global__ void k_scan() {
    __shared__ int warp_sums[32];
    __shared__ int s_carry;
    int tid = threadIdx.x, lane = tid & 31, wid = tid >> 5;
    if (tid == 0) s_carry = 0;
    __syncthreads();
    for (int base = 0; base < N_NODES; base += 1024) {
        int i = base + tid;
        int v = (i < N_NODES) ? g_cnt[i] : 0;
        if (i < N_NODES) g_inv[i] = 1.0f / (float)max(v, 1);
        int x = v;
        #pragma unroll
        for (int off = 1; off < 32; off <<= 1) {
            int y = __shfl_up_sync(0xffffffffu, x, off);
            if (lane >= off) x += y;
        }
        if (lane == 31) warp_sums[wid] = x;
        __syncthreads();
        if (wid == 0) {
            int w = warp_sums[lane];
            #pragma unroll
            for (int off = 1; off < 32; off <<= 1) {
                int y = __shfl_up_sync(0xffffffffu, w, off);
                if (lane >= off) w += y;
            }
            warp_sums[lane] = w;
        }
        __syncthreads();
        int incl = x + (wid > 0 ? warp_sums[wid - 1] : 0);
        int excl = incl - v;
        if (i < N_NODES) g_rowptr[i] = s_carry + excl;
        __syncthreads();
        if (tid == 0) s_carry += warp_sums[31];
        __syncthreads();
    }
    if (threadIdx.x == 0) g_rowptr[N_NODES] = s_carry;
}

__global__ void k_build(const int* __restrict__ ei) {
    int e = blockIdx.x * blockDim.x + threadIdx.x;
    if (e >= N_EDGES) return;
    int d = ei[N_EDGES + e];
    int s = ei[e];
    int pos = g_rowptr[d] + atomicAdd(&g_cursor[d], 1);
    g_col[pos] = s;
}

// ---------------- split fp32 weight -> (hi, lo) fp16 ----------------
__global__ void k_split(const float* __restrict__ w, int n,
                        __half* __restrict__ hi, __half* __restrict__ lo) {
    int i = blockIdx.x * blockDim.x + threadIdx.x;
    if (i >= n) return;
    float x = w[i];
    __half h = __float2half_rn(x);
    hi[i] = h;
    lo[i] = __float2half_rn(x - __half2float(h));
}

// ---------------- mma helpers ----------------
__device__ __forceinline__ void ldsm4(uint32_t (&r)[4], uint32_t addr) {
    asm volatile("ldmatrix.sync.aligned.m8n8.x4.shared.b16 {%0,%1,%2,%3}, [%4];"
                 : "=r"(r[0]), "=r"(r[1]), "=r"(r[2]), "=r"(r[3]) : "r"(addr));
}
__device__ __forceinline__ void ldsm4t(uint32_t (&r)[4], uint32_t addr) {
    asm volatile("ldmatrix.sync.aligned.m8n8.x4.trans.shared.b16 {%0,%1,%2,%3}, [%4];"
                 : "=r"(r[0]), "=r"(r[1]), "=r"(r[2]), "=r"(r[3]) : "r"(addr));
}
__device__ __forceinline__ void mma16816h(float (&c)[4], const uint32_t (&a)[4],
                                          uint32_t b0, uint32_t b1) {
    asm volatile(
        "mma.sync.aligned.m16n8k16.row.col.f32.f16.f16.f32 "
        "{%0,%1,%2,%3}, {%4,%5,%6,%7}, {%8,%9}, {%0,%1,%2,%3};"
        : "+f"(c[0]), "+f"(c[1]), "+f"(c[2]), "+f"(c[3])
        : "r"(a[0]), "r"(a[1]), "r"(a[2]), "r"(a[3]), "r"(b0), "r"(b1));
}

#define SA_STR 40
#define SB_STR 136

// ---------------- tensor-core GEMM (fp16, 2-term weight split, single-buffer, R9) ----------
__global__ void __launch_bounds__(256, 2) k_gemm_tc(
    const void* __restrict__ Av,
    const __half* __restrict__ Bh, const __half* __restrict__ Bl,
    const float* __restrict__ bias, void* __restrict__ Cv,
    int M, int K, float alpha, int do_relu, int in_half, int out_half,
    int tile_off, const int* __restrict__ pool_batch)
{
    __shared__ __half sA[128 * SA_STR];
    __shared__ __half sBh[32 * SB_STR];
    __shared__ __half sBl[32 * SB_STR];

    const int tid  = threadIdx.x;
    const int lane = tid & 31;
    const int warp = tid >> 5;
    const int wm   = warp & 3;
    const int wn   = warp >> 2;
    const int m0   = (blockIdx.x + tile_off) * 128;

    const int ar = tid >> 1;
    const int ac = (tid & 1) * 16;
    const int br = tid >> 3;
    const int bc = (tid & 7) * 16;

    const uint32_t baseA  = (uint32_t)__cvta_generic_to_shared(sA);
    const uint32_t baseBh = (uint32_t)__cvta_generic_to_shared(sBh);
    const uint32_t baseBl = (uint32_t)__cvta_generic_to_shared(sBl);

    float acc[2][8][4];
    #pragma unroll
    for (int t = 0; t < 2; t++)
        #pragma unroll
        for (int n = 0; n < 8; n++)
            #pragma unroll
            for (int j = 0; j < 4; j++) acc[t][n][j] = 0.0f;

    const int arow = m0 + ar;
    const bool aok = (arow < M);
    const int T = K >> 5;

    const float*  Af = (const float*)Av;
    const __half* Ah = (const __half*)Av;

    uint4 ha0, ha1;
    uint4 pbh0, pbh1, pbl0, pbl1;

    {
        ha0 = make_uint4(0u, 0u, 0u, 0u); ha1 = ha0;
        if (aok) {
            if (in_half) {
                const uint4* ap = (const uint4*)(Ah + (size_t)arow * K + ac);
                ha0 = ap[0]; ha1 = ap[1];
            } else {
                const float4* ap = (const float4*)(Af + (size_t)arow * K + ac);
                float4 f0 = ap[0], f1 = ap[1], f2 = ap[2], f3 = ap[3];
                __half2 h0 = __floats2half2_rn(f0.x, f0.y);
                __half2 h1 = __floats2half2_rn(f0.z, f0.w);
                __half2 h2 = __floats2half2_rn(f1.x, f1.y);
                __half2 h3 = __floats2half2_rn(f1.z, f1.w);
                __half2 h4 = __floats2half2_rn(f2.x, f2.y);
                __half2 h5 = __floats2half2_rn(f2.z, f2.w);
                __half2 h6 = __floats2half2_rn(f3.x, f3.y);
                __half2 h7 = __floats2half2_rn(f3.z, f3.w);
                ha0 = make_uint4(*(uint32_t*)&h0, *(uint32_t*)&h1, *(uint32_t*)&h2, *(uint32_t*)&h3);
                ha1 = make_uint4(*(uint32_t*)&h4, *(uint32_t*)&h5, *(uint32_t*)&h6, *(uint32_t*)&h7);
            }
        }
        const uint4* bph = (const uint4*)(Bh + (size_t)br * HDIM + bc);
        const uint4* bpl = (const uint4*)(Bl + (size_t)br * HDIM + bc);
        pbh0 = bph[0]; pbh1 = bph[1];
        pbl0 = bpl[0]; pbl1 = bpl[1];
    }

    for (int t = 0; t < T; t++) {
        {
            uint4* da = (uint4*)&sA[ar * SA_STR + ac];
            da[0] = ha0; da[1] = ha1;
            *(uint4*)&sBh[br * SB_STR + bc]     = pbh0;
            *(uint4*)&sBh[br * SB_STR + bc + 8] = pbh1;
            *(uint4*)&sBl[br * SB_STR + bc]     = pbl0;
            *(uint4*)&sBl[br * SB_STR + bc + 8] = pbl1;
        }
        __syncthreads();

        if (t + 1 < T) {
            const int k0 = (t + 1) << 5;
            ha0 = make_uint4(0u, 0u, 0u, 0u); ha1 = ha0;
            if (aok) {
                if (in_half) {
                    const uint4* ap = (const uint4*)(Ah + (size_t)arow * K + k0 + ac);
                    ha0 = ap[0]; ha1 = ap[1];
                } else {
                    const float4* ap = (const float4*)(Af + (size_t)arow * K + k0 + ac);
                    float4 f0 = ap[0], f1 = ap[1], f2 = ap[2], f3 = ap[3];
                    __half2 h0 = __floats2half2_rn(f0.x, f0.y);
                    __half2 h1 = __floats2half2_rn(f0.z, f0.w);
                    __half2 h2 = __floats2half2_rn(f1.x, f1.y);
                    __half2 h3 = __floats2half2_rn(f1.z, f1.w);
                    __half2 h4 = __floats2half2_rn(f2.x, f2.y);
                    __half2 h5 = __floats2half2_rn(f2.z, f2.w);
                    __half2 h6 = __floats2half2_rn(f3.x, f3.y);
                    __half2 h7 = __floats2half2_rn(f3.z, f3.w);
                    ha0 = make_uint4(*(uint32_t*)&h0, *(uint32_t*)&h1, *(uint32_t*)&h2, *(uint32_t*)&h3);
                    ha1 = make_uint4(*(uint32_t*)&h4, *(uint32_t*)&h5, *(uint32_t*)&h6, *(uint32_t*)&h7);
                }
            }
            const uint4* bph = (const uint4*)(Bh + (size_t)(k0 + br) * HDIM + bc);
            const uint4* bpl = (const uint4*)(Bl + (size_t)(k0 + br) * HDIM + bc);
            pbh0 = bph[0]; pbh1 = bph[1];
            pbl0 = bpl[0]; pbl1 = bpl[1];
        }

        #pragma unroll
        for (int ks = 0; ks < 2; ks++) {
            uint32_t a[2][4];
            #pragma unroll
            for (int tt = 0; tt < 2; tt++) {
                int r = wm * 32 + tt * 16 + (lane & 15);
                int c = ks * 16 + (lane >> 4) * 8;
                ldsm4(a[tt], baseA + (r * SA_STR + c) * 2);
            }
            #pragma unroll
            for (int p = 0; p < 4; p++) {
                int r = ks * 16 + (lane & 7) + ((lane >> 3) & 1) * 8;
                int c = wn * 64 + p * 16 + (lane >> 4) * 8;
                uint32_t bh[4], bl[4];
                ldsm4t(bh, baseBh + (r * SB_STR + c) * 2);
                ldsm4t(bl, baseBl + (r * SB_STR + c) * 2);
                #pragma unroll
                for (int tt = 0; tt < 2; tt++) {
                    mma16816h(acc[tt][2 * p],     a[tt], bh[0], bh[1]);
                    mma16816h(acc[tt][2 * p],     a[tt], bl[0], bl[1]);
                    mma16816h(acc[tt][2 * p + 1], a[tt], bh[2], bh[3]);
                    mma16816h(acc[tt][2 * p + 1], a[tt], bl[2], bl[3]);
                }
            }
        }
        __syncthreads();
    }

    // ---- epilogue ----
    #pragma unroll
    for (int t = 0; t < 2; t++) {
        #pragma unroll
        for (int nt = 0; nt < 8; nt++) {
            int col = wn * 64 + nt * 8 + (lane & 3) * 2;
            float b0 = 0.f, b1 = 0.f;
            if (bias) { b0 = bias[col]; b1 = bias[col + 1]; }
            int r0 = m0 + wm * 32 + t * 16 + (lane >> 2);
            int r1 = r0 + 8;
            float v00 = acc[t][nt][0] * alpha + b0;
            float v01 = acc[t][nt][1] * alpha + b1;
            float v10 = acc[t][nt][2] * alpha + b0;
            float v11 = acc[t][nt][3] * alpha + b1;
            if (do_relu) {
                v00 = fmaxf(v00, 0.f); v01 = fmaxf(v01, 0.f);
                v10 = fmaxf(v10, 0.f); v11 = fmaxf(v11, 0.f);
            }
            if (pool_batch) {
                if (r0 < M) {
                    int g = pool_batch[r0];
                    atomicAdd(&g_zsum[g * HDIM + col], v00);
                    atomicAdd(&g_zsum[g * HDIM + col + 1], v01);
                }
                if (r1 < M) {
                    int g = pool_batch[r1];
                    atomicAdd(&g_zsum[g * HDIM + col], v10);
                    atomicAdd(&g_zsum[g * HDIM + col + 1], v11);
                }
            } else if (out_half) {
                __half* C = (__half*)Cv;
                if (r0 < M) {
                    __half2 o = __floats2half2_rn(v00, v01);
                    *(__half2*)&C[(size_t)r0 * HDIM + col] = o;
                }
                if (r1 < M) {
                    __half2 o = __floats2half2_rn(v10, v11);
                    *(__half2*)&C[(size_t)r1 * HDIM + col] = o;
                }
            } else {
                float* C = (float*)Cv;
                if (r0 < M) { float2 o = {v00, v01}; *(float2*)&C[(size_t)r0 * HDIM + col] = o; }
                if (r1 < M) { float2 o = {v10, v11}; *(float2*)&C[(size_t)r1 * HDIM + col] = o; }
            }
        }
    }
}

// ------ CSR mean-aggregation, 8-way unrolled index batch (same fp32 sum order) ------
__global__ void __launch_bounds__(256) k_agg(const __half* __restrict__ hin,
                                             __half* __restrict__ aout,
                                             int node0, int node1)
{
    int gt = blockIdx.x * 256 + threadIdx.x;
    int node = node0 + (gt >> 5);
    int lane = gt & 31;
    if (node >= node1) return;
    int beg = g_rowptr[node];
    int end = g_rowptr[node + 1];
    float ax = 0.f, ay = 0.f, az = 0.f, aw = 0.f;
    int e = beg;
    for (; e + 8 <= end; e += 8) {
        int s[8];
        #pragma unroll
        for (int j = 0; j < 8; j++) s[j] = __ldg(&g_col[e + j]);
        uint2 u[8];
        #pragma unroll
        for (int j = 0; j < 8; j++)
            u[j] = *(const uint2*)&hin[(size_t)s[j] * HDIM + lane * 4];
        #pragma unroll
        for (int j = 0; j < 8; j++) {
            float2 a = __half22float2(*(__half2*)&u[j].x);
            float2 b = __half22float2(*(__half2*)&u[j].y);
            ax += a.x; ay += a.y; az += b.x; aw += b.y;
        }
    }
    for (; e < end; e++) {
        int s = __ldg(&g_col[e]);
        uint2 u = *(const uint2*)&hin[(size_t)s * HDIM + lane * 4];
        float2 a = __half22float2(*(__half2*)&u.x), b = __half22float2(*(__half2*)&u.y);
        ax += a.x; ay += a.y; az += b.x; aw += b.y;
    }
    float sc = g_inv[node];
    __half2 o0 = __floats2half2_rn(ax * sc, ay * sc);
    __half2 o1 = __floats2half2_rn(az * sc, aw * sc);
    uint2 o;
    o.x = *(uint32_t*)&o0;
    o.y = *(uint32_t*)&o1;
    *(uint2*)&aout[(size_t)node * HDIM + lane * 4] = o;
}

// ---------------- classifier head: one block per graph ----------------
__global__ void __launch_bounds__(128) k_head(
    const float* __restrict__ c1w, const float* __restrict__ c1b,
    const float* __restrict__ c2w, const float* __restrict__ c2b,
    const float* __restrict__ c3w, const float* __restrict__ c3b,
    float* __restrict__ dout)
{
    __shared__ float z[HDIM], o1[HDIM], o2[HDIM];
    int g = blockIdx.x;
    int c = threadIdx.x;
    float cnt = (float)max(g_zcnt[g], 1);
    float zv = g_zsum[g * HDIM + c] / cnt;
    z[c] = zv;
    dout[NGRAPH * OUT_DIM + g * HDIM + c] = zv;
    __syncthreads();
    float s = c1b[c];
    #pragma unroll 8
    for (int k = 0; k < HDIM; k++) s += z[k] * c1w[k * HDIM + c];
    o1[c] = fmaxf(s, 0.f);
    __syncthreads();
    s = c2b[c];
    #pragma unroll 8
    for (int k = 0; k < HDIM; k++) s += o1[k] * c2w[k * HDIM + c];
    o2[c] = fmaxf(s, 0.f);
    __syncthreads();
    if (c < OUT_DIM) {
        s = c3b[c];
        #pragma unroll 8
        for (int k = 0; k < HDIM; k++) s += o2[k] * c3w[k * OUT_DIM + c];
        dout[g * OUT_DIM + c] = s;
    }
}

// ---------------- side stream/events (created at static init) ----------------
static cudaStream_t s_side = nullptr;
static cudaEvent_t  s_evFork = nullptr, s_evJoin = nullptr;
static cudaEvent_t  s_evA[4], s_evB[4];
namespace {
struct SideInit {
    SideInit() {
        cudaStreamCreateWithFlags(&s_side, cudaStreamNonBlocking);
        cudaEventCreateWithFlags(&s_evFork, cudaEventDisableTiming);
        cudaEventCreateWithFlags(&s_evJoin, cudaEventDisableTiming);
        for (int i = 0; i < 4; i++) {
            cudaEventCreateWithFlags(&s_evA[i], cudaEventDisableTiming);
            cudaEventCreateWithFlags(&s_evB[i], cudaEventDisableTiming);
        }
    }
};
static SideInit s_sideInit;
}

// ---------------- launch ----------------
extern "C" void kernel_launch(void* const* d_in, const int* in_sizes, int n_in,
                              void* d_out, int out_size)
{
    const float* x     = (const float*)d_in[0];
    const int*   ei    = (const int*)  d_in[2];
    const int*   batch = (const int*)  d_in[3];
    const float* lin_w = (const float*)d_in[4];
    const float* lin_b = (const float*)d_in[5];
    const float* tp_w1 = (const float*)d_in[6];
    const float* tp_w2 = (const float*)d_in[7];
    const float* tp_w3 = (const float*)d_in[8];
    const float* c1w   = (const float*)d_in[9];
    const float* c1b   = (const float*)d_in[10];
    const float* c2w   = (const float*)d_in[11];
    const float* c2b   = (const float*)d_in[12];
    const float* c3w   = (const float*)d_in[13];
    const float* c3b   = (const float*)d_in[14];
    float* out = (float*)d_out;

    __half *hA, *hB, *agg, *pBh, *pBl, *pW1h, *pW1l, *pW2h, *pW2l, *pW3h, *pW3l;
    cudaGetSymbolAddress((void**)&hA, g_h16a);
    cudaGetSymbolAddress((void**)&hB, g_h16b);
    cudaGetSymbolAddress((void**)&agg, g_agg);
    cudaGetSymbolAddress((void**)&pBh, g_Bh);
    cudaGetSymbolAddress((void**)&pBl, g_Bl);
    cudaGetSymbolAddress((void**)&pW1h, g_W1h);
    cudaGetSymbolAddress((void**)&pW1l, g_W1l);
    cudaGetSymbolAddress((void**)&pW2h, g_W2h);
    cudaGetSymbolAddress((void**)&pW2l, g_W2l);
    cudaGetSymbolAddress((void**)&pW3h, g_W3h);
    cudaGetSymbolAddress((void**)&pW3l, g_W3l);

    const int TB = 256;
    const int T1 = TILE_SPLIT;              // 196 tiles -> rows [0, 25088)
    const int T2 = GEMM_TILES - TILE_SPLIT; // 195 tiles -> rows [25088, 50000)
    const int aggGrid1 = (NODE_SPLIT * 32 + TB - 1) / TB;
    const int aggGrid2 = ((N_NODES - NODE_SPLIT) * 32 + TB - 1) / TB;

    // ---- fork side stream: CSR build + tp-weight splits ----
    cudaEventRecord(s_evFork, 0);
    cudaStreamWaitEvent(s_side, s_evFork, 0);

    k_zero<<<(N_NODES + TB - 1) / TB, TB, 0, s_side>>>();
    k_count<<<(N_EDGES + TB - 1) / TB, TB, 0, s_side>>>(ei, batch);
    k_scan<<<1, 1024, 0, s_side>>>();
    k_build<<<(N_EDGES + TB - 1) / TB, TB, 0, s_side>>>(ei);
    k_split<<<(HDIM * HDIM + TB - 1) / TB, TB, 0, s_side>>>(tp_w1, HDIM * HDIM, pW1h, pW1l);
    k_split<<<(HDIM * HDIM + TB - 1) / TB, TB, 0, s_side>>>(tp_w2, HDIM * HDIM, pW2h, pW2l);
    k_split<<<(HDIM * HDIM + TB - 1) / TB, TB, 0, s_side>>>(tp_w3, HDIM * HDIM, pW3h, pW3l);
    cudaEventRecord(s_evJoin, s_side);

    // ---- main stream: lin split + lin GEMM -> buffer A ----
    k_split<<<(F_INDIM * HDIM + TB - 1) / TB, TB>>>(lin_w, F_INDIM * HDIM, pBh, pBl);
    k_gemm_tc<<<GEMM_TILES, TB>>>(x, pBh, pBl, lin_b, hA, N_NODES, F_INDIM,
                                  1.0f, 1, 0, 1, 0, nullptr);

    cudaStreamWaitEvent(0, s_evJoin, 0);

    // ---- convs with split-node agg/GEMM overlap; features ping-pong hA <-> hB ----
    const __half* Wh[3] = {pW1h, pW2h, pW3h};
    const __half* Wl[3] = {pW1l, pW2l, pW3l};
    __half* cur = hA;
    __half* nxt = hB;
    for (int k = 0; k < 3; k++) {
        int relu = (k < 2) ? 1 : 0;
        const int* pool = (k == 2) ? batch : nullptr;
        int oh = (k == 2) ? 0 : 1;
        void* cout = (k == 2) ? nullptr : (void*)nxt;

        cudaEventRecord(s_evA[k], 0);
        cudaStreamWaitEvent(s_side, s_evA[k], 0);

        // aggs read cur -> write agg; GEMMs read agg -> write nxt (no WAR)
        k_agg<<<aggGrid2, TB, 0, s_side>>>(cur, agg, NODE_SPLIT, N_NODES);
        k_agg<<<aggGrid1, TB, 0, 0>>>(cur, agg, 0, NODE_SPLIT);

        k_gemm_tc<<<T1, TB, 0, 0>>>(agg, Wh[k], Wl[k], nullptr, cout,
                                    N_NODES, HDIM, TP_NORM, relu, 1, oh,
                                    0, pool);
        k_gemm_tc<<<T2, TB, 0, s_side>>>(agg, Wh[k], Wl[k], nullptr, cout,
                                         N_NODES, HDIM, TP_NORM, relu, 1, oh,
                                         TILE_SPLIT, pool);

        cudaEventRecord(s_evB[k], s_side);
        cudaStreamWaitEvent(0, s_evB[k], 0);

        __half* tmp = cur; cur = nxt; nxt = tmp;
    }

    // head
    k_head<<<NGRAPH, HDIM>>>(c1w, c1b, c2w, c2b, c3w, c3b, out);
}

// round 16
// speedup vs baseline: 1.6727x; 1.1270x over previous
#include <cuda_runtime.h>
#include <cuda_fp16.h>
#include <cstdint>

#define N_NODES 50000
#define N_EDGES 1600000
#define F_INDIM 1280
#define HDIM    128
#define NGRAPH  64
#define OUT_DIM 2
#define TP_NORM 0.024933891662820262f  /* (0.5/sqrt(pi))/sqrt(128) */

#define TILE_SPLIT 196                     /* m-tiles in half1 */
#define NODE_SPLIT (TILE_SPLIT * 128)      /* 25088 */
#define GEMM_TILES ((N_NODES + 127) / 128) /* 391 */

// ---------------- device scratch (no allocations allowed) ----------------
__device__ __half g_h16a[N_NODES * HDIM];   // ping-pong feature buffers
__device__ __half g_h16b[N_NODES * HDIM];
__device__ __half g_agg[N_NODES * HDIM];
__device__ int    g_cnt[N_NODES];
__device__ int    g_cursor[N_NODES];
__device__ int    g_rowptr[N_NODES + 1];
__device__ int    g_col[N_EDGES];
__device__ float  g_inv[N_NODES];
__device__ float  g_zsum[NGRAPH * HDIM];
__device__ int    g_zcnt[NGRAPH];
__device__ __half g_Bh[F_INDIM * HDIM];
__device__ __half g_Bl[F_INDIM * HDIM];
__device__ __half g_W1h[HDIM * HDIM], g_W1l[HDIM * HDIM];
__device__ __half g_W2h[HDIM * HDIM], g_W2l[HDIM * HDIM];
__device__ __half g_W3h[HDIM * HDIM], g_W3l[HDIM * HDIM];

// ---------------- small setup kernels ----------------
__global__ void k_zero() {
    int i = blockIdx.x * blockDim.x + threadIdx.x;
    if (i < N_NODES) { g_cnt[i] = 0; g_cursor[i] = 0; }
    if (i < NGRAPH * HDIM) g_zsum[i] = 0.0f;
    if (i < NGRAPH) g_zcnt[i] = 0;
}

__global__ void k_count(const int* __restrict__ ei, const int* __restrict__ batch) {
    int e = blockIdx.x * blockDim.x + threadIdx.x;
    if (e < N_EDGES) atomicAdd(&g_cnt[ei[N_EDGES + e]], 1);
    if (e < N_NODES) atomicAdd(&g_zcnt[batch[e]], 1);
}

__global__ void k_scan() {
    __shared__ int warp_sums[32];
    __shared__ int s_carry;
    int tid = threadIdx.x, lane = tid & 31, wid = tid >> 5;
    if (tid == 0) s_carry = 0;
    __syncthreads();
    for (int base = 0; base < N_NODES; base += 1024) {
        int i = base + tid;
        int v = (i < N_NODES) ? g_cnt[i] : 0;
        if (i < N_NODES) g_inv[i] = 1.0f / (float)max(v, 1);
        int x = v;
        #pragma unroll
        for (int off = 1; off < 32; off <<= 1) {
            int y = __shfl_up_sync(0xffffffffu, x, off);
            if (lane >= off) x += y;
        }
        if (lane == 31) warp_sums[wid] = x;
        __syncthreads();
        if (wid == 0) {
            int w = warp_sums[lane];
            #pragma unroll
            for (int off = 1; off < 32; off <<= 1) {
                int y = __shfl_up_sync(0xffffffffu, w, off);
                if (lane >= off) w += y;
            }
            warp_sums[lane] = w;
        }
        __syncthreads();
        int incl = x + (wid > 0 ? warp_sums[wid - 1] : 0);
        int excl = incl - v;
        if (i < N_NODES) g_rowptr[i] = s_carry + excl;
        __syncthreads();
        if (tid == 0) s_carry += warp_sums[31];
        __syncthreads();
    }
    if (threadIdx.x == 0) g_rowptr[N_NODES] = s_carry;
}

__global__ void k_build(const int* __restrict__ ei) {
    int e = blockIdx.x * blockDim.x + threadIdx.x;
    if (e >= N_EDGES) return;
    int d = ei[N_EDGES + e];
    int s = ei[e];
    int pos = g_rowptr[d] + atomicAdd(&g_cursor[d], 1);
    g_col[pos] = s;
}

// ---------------- split fp32 weight -> (hi, lo) fp16 ----------------
__global__ void k_split(const float* __restrict__ w, int n,
                        __half* __restrict__ hi, __half* __restrict__ lo) {
    int i = blockIdx.x * blockDim.x + threadIdx.x;
    if (i >= n) return;
    float x = w[i];
    __half h = __float2half_rn(x);
    hi[i] = h;
    lo[i] = __float2half_rn(x - __half2float(h));
}

// ---------------- mma helpers ----------------
__device__ __forceinline__ void ldsm4(uint32_t (&r)[4], uint32_t addr) {
    asm volatile("ldmatrix.sync.aligned.m8n8.x4.shared.b16 {%0,%1,%2,%3}, [%4];"
                 : "=r"(r[0]), "=r"(r[1]), "=r"(r[2]), "=r"(r[3]) : "r"(addr));
}
__device__ __forceinline__ void ldsm4t(uint32_t (&r)[4], uint32_t addr) {
    asm volatile("ldmatrix.sync.aligned.m8n8.x4.trans.shared.b16 {%0,%1,%2,%3}, [%4];"
                 : "=r"(r[0]), "=r"(r[1]), "=r"(r[2]), "=r"(r[3]) : "r"(addr));
}
__device__ __forceinline__ void mma16816h(float (&c)[4], const uint32_t (&a)[4],
                                          uint32_t b0, uint32_t b1) {
    asm volatile(
        "mma.sync.aligned.m16n8k16.row.col.f32.f16.f16.f32 "
        "{%0,%1,%2,%3}, {%4,%5,%6,%7}, {%8,%9}, {%0,%1,%2,%3};"
        : "+f"(c[0]), "+f"(c[1]), "+f"(c[2]), "+f"(c[3])
        : "r"(a[0]), "r"(a[1]), "r"(a[2]), "r"(a[3]), "r"(b0), "r"(b1));
}

#define SA_STR 40
#define SB_STR 136

// -------- tensor-core GEMM (fp16, USE_BL selects 1- or 2-term weight, single-buffer) -------
template <int USE_BL>
__global__ void __launch_bounds__(256, 2) k_gemm_tc(
    const void* __restrict__ Av,
    const __half* __restrict__ Bh, const __half* __restrict__ Bl,
    const float* __restrict__ bias, void* __restrict__ Cv,
    int M, int K, float alpha, int do_relu, int in_half, int out_half,
    int tile_off, const int* __restrict__ pool_batch)
{
    __shared__ __half sA[128 * SA_STR];
    __shared__ __half sBh[32 * SB_STR];
    __shared__ __half sBl[USE_BL ? 32 * SB_STR : 2];

    const int tid  = threadIdx.x;
    const int lane = tid & 31;
    const int warp = tid >> 5;
    const int wm   = warp & 3;
    const int wn   = warp >> 2;
    const int m0   = (blockIdx.x + tile_off) * 128;

    const int ar = tid >> 1;
    const int ac = (tid & 1) * 16;
    const int br = tid >> 3;
    const int bc = (tid & 7) * 16;

    const uint32_t baseA  = (uint32_t)__cvta_generic_to_shared(sA);
    const uint32_t baseBh = (uint32_t)__cvta_generic_to_shared(sBh);
    const uint32_t baseBl = (uint32_t)__cvta_generic_to_shared(sBl);

    float acc[2][8][4];
    #pragma unroll
    for (int t = 0; t < 2; t++)
        #pragma unroll
        for (int n = 0; n < 8; n++)
            #pragma unroll
            for (int j = 0; j < 4; j++) acc[t][n][j] = 0.0f;

    const int arow = m0 + ar;
    const bool aok = (arow < M);
    const int T = K >> 5;

    const float*  Af = (const float*)Av;
    const __half* Ah = (const __half*)Av;

    uint4 ha0, ha1;
    uint4 pbh0, pbh1, pbl0, pbl1;

    {
        ha0 = make_uint4(0u, 0u, 0u, 0u); ha1 = ha0;
        if (aok) {
            if (in_half) {
                const uint4* ap = (const uint4*)(Ah + (size_t)arow * K + ac);
                ha0 = ap[0]; ha1 = ap[1];
            } else {
                const float4* ap = (const float4*)(Af + (size_t)arow * K + ac);
                float4 f0 = ap[0], f1 = ap[1], f2 = ap[2], f3 = ap[3];
                __half2 h0 = __floats2half2_rn(f0.x, f0.y);
                __half2 h1 = __floats2half2_rn(f0.z, f0.w);
                __half2 h2 = __floats2half2_rn(f1.x, f1.y);
                __half2 h3 = __floats2half2_rn(f1.z, f1.w);
                __half2 h4 = __floats2half2_rn(f2.x, f2.y);
                __half2 h5 = __floats2half2_rn(f2.z, f2.w);
                __half2 h6 = __floats2half2_rn(f3.x, f3.y);
                __half2 h7 = __floats2half2_rn(f3.z, f3.w);
                ha0 = make_uint4(*(uint32_t*)&h0, *(uint32_t*)&h1, *(uint32_t*)&h2, *(uint32_t*)&h3);
                ha1 = make_uint4(*(uint32_t*)&h4, *(uint32_t*)&h5, *(uint32_t*)&h6, *(uint32_t*)&h7);
            }
        }
        const uint4* bph = (const uint4*)(Bh + (size_t)br * HDIM + bc);
        pbh0 = bph[0]; pbh1 = bph[1];
        if (USE_BL) {
            const uint4* bpl = (const uint4*)(Bl + (size_t)br * HDIM + bc);
            pbl0 = bpl[0]; pbl1 = bpl[1];
        }
    }

    for (int t = 0; t < T; t++) {
        {
            uint4* da = (uint4*)&sA[ar * SA_STR + ac];
            da[0] = ha0; da[1] = ha1;
            *(uint4*)&sBh[br * SB_STR + bc]     = pbh0;
            *(uint4*)&sBh[br * SB_STR + bc + 8] = pbh1;
            if (USE_BL) {
                *(uint4*)&sBl[br * SB_STR + bc]     = pbl0;
                *(uint4*)&sBl[br * SB_STR + bc + 8] = pbl1;
            }
        }
        __syncthreads();

        if (t + 1 < T) {
            const int k0 = (t + 1) << 5;
            ha0 = make_uint4(0u, 0u, 0u, 0u); ha1 = ha0;
            if (aok) {
                if (in_half) {
                    const uint4* ap = (const uint4*)(Ah + (size_t)arow * K + k0 + ac);
                    ha0 = ap[0]; ha1 = ap[1];
                } else {
                    const float4* ap = (const float4*)(Af + (size_t)arow * K + k0 + ac);
                    float4 f0 = ap[0], f1 = ap[1], f2 = ap[2], f3 = ap[3];
                    __half2 h0 = __floats2half2_rn(f0.x, f0.y);
                    __half2 h1 = __floats2half2_rn(f0.z, f0.w);
                    __half2 h2 = __floats2half2_rn(f1.x, f1.y);
                    __half2 h3 = __floats2half2_rn(f1.z, f1.w);
                    __half2 h4 = __floats2half2_rn(f2.x, f2.y);
                    __half2 h5 = __floats2half2_rn(f2.z, f2.w);
                    __half2 h6 = __floats2half2_rn(f3.x, f3.y);
                    __half2 h7 = __floats2half2_rn(f3.z, f3.w);
                    ha0 = make_uint4(*(uint32_t*)&h0, *(uint32_t*)&h1, *(uint32_t*)&h2, *(uint32_t*)&h3);
                    ha1 = make_uint4(*(uint32_t*)&h4, *(uint32_t*)&h5, *(uint32_t*)&h6, *(uint32_t*)&h7);
                }
            }
            const uint4* bph = (const uint4*)(Bh + (size_t)(k0 + br) * HDIM + bc);
            pbh0 = bph[0]; pbh1 = bph[1];
            if (USE_BL) {
                const uint4* bpl = (const uint4*)(Bl + (size_t)(k0 + br) * HDIM + bc);
                pbl0 = bpl[0]; pbl1 = bpl[1];
            }
        }

        #pragma unroll
        for (int ks = 0; ks < 2; ks++) {
            uint32_t a[2][4];
            #pragma unroll
            for (int tt = 0; tt < 2; tt++) {
                int r = wm * 32 + tt * 16 + (lane & 15);
                int c = ks * 16 + (lane >> 4) * 8;
                ldsm4(a[tt], baseA + (r * SA_STR + c) * 2);
            }
            #pragma unroll
            for (int p = 0; p < 4; p++) {
                int r = ks * 16 + (lane & 7) + ((lane >> 3) & 1) * 8;
                int c = wn * 64 + p * 16 + (lane >> 4) * 8;
                uint32_t bh[4];
                ldsm4t(bh, baseBh + (r * SB_STR + c) * 2);
                if (USE_BL) {
                    uint32_t bl[4];
                    ldsm4t(bl, baseBl + (r * SB_STR + c) * 2);
                    #pragma unroll
                    for (int tt = 0; tt < 2; tt++) {
                        mma16816h(acc[tt][2 * p],     a[tt], bh[0], bh[1]);
                        mma16816h(acc[tt][2 * p],     a[tt], bl[0], bl[1]);
                        mma16816h(acc[tt][2 * p + 1], a[tt], bh[2], bh[3]);
                        mma16816h(acc[tt][2 * p + 1], a[tt], bl[2], bl[3]);
                    }
                } else {
                    #pragma unroll
                    for (int tt = 0; tt < 2; tt++) {
                        mma16816h(acc[tt][2 * p],     a[tt], bh[0], bh[1]);
                        mma16816h(acc[tt][2 * p + 1], a[tt], bh[2], bh[3]);
                    }
                }
            }
        }
        __syncthreads();
    }

    // ---- epilogue ----
    #pragma unroll
    for (int t = 0; t < 2; t++) {
        #pragma unroll
        for (int nt = 0; nt < 8; nt++) {
            int col = wn * 64 + nt * 8 + (lane & 3) * 2;
            float b0 = 0.f, b1 = 0.f;
            if (bias) { b0 = bias[col]; b1 = bias[col + 1]; }
            int r0 = m0 + wm * 32 + t * 16 + (lane >> 2);
            int r1 = r0 + 8;
            float v00 = acc[t][nt][0] * alpha + b0;
            float v01 = acc[t][nt][1] * alpha + b1;
            float v10 = acc[t][nt][2] * alpha + b0;
            float v11 = acc[t][nt][3] * alpha + b1;
            if (do_relu) {
                v00 = fmaxf(v00, 0.f); v01 = fmaxf(v01, 0.f);
                v10 = fmaxf(v10, 0.f); v11 = fmaxf(v11, 0.f);
            }
            if (pool_batch) {
                if (r0 < M) {
                    int g = pool_batch[r0];
                    atomicAdd(&g_zsum[g * HDIM + col], v00);
                    atomicAdd(&g_zsum[g * HDIM + col + 1], v01);
                }
                if (r1 < M) {
                    int g = pool_batch[r1];
                    atomicAdd(&g_zsum[g * HDIM + col], v10);
                    atomicAdd(&g_zsum[g * HDIM + col + 1], v11);
                }
            } else if (out_half) {
                __half* C = (__half*)Cv;
                if (r0 < M) {
                    __half2 o = __floats2half2_rn(v00, v01);
                    *(__half2*)&C[(size_t)r0 * HDIM + col] = o;
                }
                if (r1 < M) {
                    __half2 o = __floats2half2_rn(v10, v11);
                    *(__half2*)&C[(size_t)r1 * HDIM + col] = o;
                }
            } else {
                float* C = (float*)Cv;
                if (r0 < M) { float2 o = {v00, v01}; *(float2*)&C[(size_t)r0 * HDIM + col] = o; }
                if (r1 < M) { float2 o = {v10, v11}; *(float2*)&C[(size_t)r1 * HDIM + col] = o; }
            }
        }
    }
}

// ------ CSR mean-aggregation, 8-way unrolled index batch (same fp32 sum order) ------
__global__ void __launch_bounds__(256) k_agg(const __half* __restrict__ hin,
                                             __half* __restrict__ aout,
                                             int node0, int node1)
{
    int gt = blockIdx.x * 256 + threadIdx.x;
    int node = node0 + (gt >> 5);
    int lane = gt & 31;
    if (node >= node1) return;
    int beg = g_rowptr[node];
    int end = g_rowptr[node + 1];
    float ax = 0.f, ay = 0.f, az = 0.f, aw = 0.f;
    int e = beg;
    for (; e + 8 <= end; e += 8) {
        int s[8];
        #pragma unroll
        for (int j = 0; j < 8; j++) s[j] = __ldg(&g_col[e + j]);
        uint2 u[8];
        #pragma unroll
        for (int j = 0; j < 8; j++)
            u[j] = *(const uint2*)&hin[(size_t)s[j] * HDIM + lane * 4];
        #pragma unroll
        for (int j = 0; j < 8; j++) {
            float2 a = __half22float2(*(__half2*)&u[j].x);
            float2 b = __half22float2(*(__half2*)&u[j].y);
            ax += a.x; ay += a.y; az += b.x; aw += b.y;
        }
    }
    for (; e < end; e++) {
        int s = __ldg(&g_col[e]);
        uint2 u = *(const uint2*)&hin[(size_t)s * HDIM + lane * 4];
        float2 a = __half22float2(*(__half2*)&u.x), b = __half22float2(*(__half2*)&u.y);
        ax += a.x; ay += a.y; az += b.x; aw += b.y;
    }
    float sc = g_inv[node];
    __half2 o0 = __floats2half2_rn(ax * sc, ay * sc);
    __half2 o1 = __floats2half2_rn(az * sc, aw * sc);
    uint2 o;
    o.x = *(uint32_t*)&o0;
    o.y = *(uint32_t*)&o1;
    *(uint2*)&aout[(size_t)node * HDIM + lane * 4] = o;
}

// ---------------- classifier head: one block per graph ----------------
__global__ void __launch_bounds__(128) k_head(
    const float* __restrict__ c1w, const float* __restrict__ c1b,
    const float* __restrict__ c2w, const float* __restrict__ c2b,
    const float* __restrict__ c3w, const float* __restrict__ c3b,
    float* __restrict__ dout)
{
    __shared__ float z[HDIM], o1[HDIM], o2[HDIM];
    int g = blockIdx.x;
    int c = threadIdx.x;
    float cnt = (float)max(g_zcnt[g], 1);
    float zv = g_zsum[g * HDIM + c] / cnt;
    z[c] = zv;
    dout[NGRAPH * OUT_DIM + g * HDIM + c] = zv;
    __syncthreads();
    float s = c1b[c];
    #pragma unroll 8
    for (int k = 0; k < HDIM; k++) s += z[k] * c1w[k * HDIM + c];
    o1[c] = fmaxf(s, 0.f);
    __syncthreads();
    s = c2b[c];
    #pragma unroll 8
    for (int k = 0; k < HDIM; k++) s += o1[k] * c2w[k * HDIM + c];
    o2[c] = fmaxf(s, 0.f);
    __syncthreads();
    if (c < OUT_DIM) {
        s = c3b[c];
        #pragma unroll 8
        for (int k = 0; k < HDIM; k++) s += o2[k] * c3w[k * OUT_DIM + c];
        dout[g * OUT_DIM + c] = s;
    }
}

// ---------------- side stream/events (created at static init) ----------------
static cudaStream_t s_side = nullptr;
static cudaEvent_t  s_evFork = nullptr, s_evJoin = nullptr;
static cudaEvent_t  s_evA[4], s_evB[4];
namespace {
struct SideInit {
    SideInit() {
        cudaStreamCreateWithFlags(&s_side, cudaStreamNonBlocking);
        cudaEventCreateWithFlags(&s_evFork, cudaEventDisableTiming);
        cudaEventCreateWithFlags(&s_evJoin, cudaEventDisableTiming);
        for (int i = 0; i < 4; i++) {
            cudaEventCreateWithFlags(&s_evA[i], cudaEventDisableTiming);
            cudaEventCreateWithFlags(&s_evB[i], cudaEventDisableTiming);
        }
    }
};
static SideInit s_sideInit;
}

// ---------------- launch ----------------
extern "C" void kernel_launch(void* const* d_in, const int* in_sizes, int n_in,
                              void* d_out, int out_size)
{
    const float* x     = (const float*)d_in[0];
    const int*   ei    = (const int*)  d_in[2];
    const int*   batch = (const int*)  d_in[3];
    const float* lin_w = (const float*)d_in[4];
    const float* lin_b = (const float*)d_in[5];
    const float* tp_w1 = (const float*)d_in[6];
    const float* tp_w2 = (const float*)d_in[7];
    const float* tp_w3 = (const float*)d_in[8];
    const float* c1w   = (const float*)d_in[9];
    const float* c1b   = (const float*)d_in[10];
    const float* c2w   = (const float*)d_in[11];
    const float* c2b   = (const float*)d_in[12];
    const float* c3w   = (const float*)d_in[13];
    const float* c3b   = (const float*)d_in[14];
    float* out = (float*)d_out;

    __half *hA, *hB, *agg, *pBh, *pBl, *pW1h, *pW1l, *pW2h, *pW2l, *pW3h, *pW3l;
    cudaGetSymbolAddress((void**)&hA, g_h16a);
    cudaGetSymbolAddress((void**)&hB, g_h16b);
    cudaGetSymbolAddress((void**)&agg, g_agg);
    cudaGetSymbolAddress((void**)&pBh, g_Bh);
    cudaGetSymbolAddress((void**)&pBl, g_Bl);
    cudaGetSymbolAddress((void**)&pW1h, g_W1h);
    cudaGetSymbolAddress((void**)&pW1l, g_W1l);
    cudaGetSymbolAddress((void**)&pW2h, g_W2h);
    cudaGetSymbolAddress((void**)&pW2l, g_W2l);
    cudaGetSymbolAddress((void**)&pW3h, g_W3h);
    cudaGetSymbolAddress((void**)&pW3l, g_W3l);

    const int TB = 256;
    const int T1 = TILE_SPLIT;              // 196 tiles -> rows [0, 25088)
    const int T2 = GEMM_TILES - TILE_SPLIT; // 195 tiles -> rows [25088, 50000)
    const int aggGrid1 = (NODE_SPLIT * 32 + TB - 1) / TB;
    const int aggGrid2 = ((N_NODES - NODE_SPLIT) * 32 + TB - 1) / TB;

    // ---- fork side stream: CSR build + tp-weight splits ----
    cudaEventRecord(s_evFork, 0);
    cudaStreamWaitEvent(s_side, s_evFork, 0);

    k_zero<<<(N_NODES + TB - 1) / TB, TB, 0, s_side>>>();
    k_count<<<(N_EDGES + TB - 1) / TB, TB, 0, s_side>>>(ei, batch);
    k_scan<<<1, 1024, 0, s_side>>>();
    k_build<<<(N_EDGES + TB - 1) / TB, TB, 0, s_side>>>(ei);
    k_split<<<(HDIM * HDIM + TB - 1) / TB, TB, 0, s_side>>>(tp_w1, HDIM * HDIM, pW1h, pW1l);
    k_split<<<(HDIM * HDIM + TB - 1) / TB, TB, 0, s_side>>>(tp_w2, HDIM * HDIM, pW2h, pW2l);
    k_split<<<(HDIM * HDIM + TB - 1) / TB, TB, 0, s_side>>>(tp_w3, HDIM * HDIM, pW3h, pW3l);
    cudaEventRecord(s_evJoin, s_side);

    // ---- main stream: lin split + lin GEMM -> buffer A (single-term fp16 weights) ----
    k_split<<<(F_INDIM * HDIM + TB - 1) / TB, TB>>>(lin_w, F_INDIM * HDIM, pBh, pBl);
    k_gemm_tc<0><<<GEMM_TILES, TB>>>(x, pBh, pBl, lin_b, hA, N_NODES, F_INDIM,
                                     1.0f, 1, 0, 1, 0, nullptr);

    cudaStreamWaitEvent(0, s_evJoin, 0);

    // ---- convs with split-node agg/GEMM overlap; features ping-pong hA <-> hB ----
    const __half* Wh[3] = {pW1h, pW2h, pW3h};
    const __half* Wl[3] = {pW1l, pW2l, pW3l};
    __half* cur = hA;
    __half* nxt = hB;
    for (int k = 0; k < 3; k++) {
        int relu = (k < 2) ? 1 : 0;
        const int* pool = (k == 2) ? batch : nullptr;
        int oh = (k == 2) ? 0 : 1;
        void* cout = (k == 2) ? nullptr : (void*)nxt;

        cudaEventRecord(s_evA[k], 0);
        cudaStreamWaitEvent(s_side, s_evA[k], 0);

        // aggs read cur -> write agg; GEMMs read agg -> write nxt (no WAR)
        k_agg<<<aggGrid2, TB, 0, s_side>>>(cur, agg, NODE_SPLIT, N_NODES);
        k_agg<<<aggGrid1, TB, 0, 0>>>(cur, agg, 0, NODE_SPLIT);

        k_gemm_tc<0><<<T1, TB, 0, 0>>>(agg, Wh[k], Wl[k], nullptr, cout,
                                       N_NODES, HDIM, TP_NORM, relu, 1, oh,
                                       0, pool);
        k_gemm_tc<0><<<T2, TB, 0, s_side>>>(agg, Wh[k], Wl[k], nullptr, cout,
                                            N_NODES, HDIM, TP_NORM, relu, 1, oh,
                                            TILE_SPLIT, pool);

        cudaEventRecord(s_evB[k], s_side);
        cudaStreamWaitEvent(0, s_evB[k], 0);

        __half* tmp = cur; cur = nxt; nxt = tmp;
    }

    // head
    k_head<<<NGRAPH, HDIM>>>(c1w, c1b, c2w, c2b, c3w, c3b, out);
}